// round 14
// baseline (speedup 1.0000x reference)
#include <cuda_runtime.h>
#include <cuda_bf16.h>
#include <math.h>
#include <stdint.h>

#define BB   2
#define SS   2048
#define DD   2048
#define HH   16
#define KVH  8
#define GG   2
#define HD   128
#define SCALE 0.08838834764831845f

typedef __nv_bfloat16 bf16;
typedef __nv_bfloat162 bf162;

// ---------------- persistent scratch ----------------
__device__ float g_q[(size_t)BB * SS * HH  * HD];   // (B,S,H,HD)
__device__ float g_k[(size_t)BB * SS * KVH * HD];   // (B,S,KV,HD)
__device__ float g_v[(size_t)BB * SS * KVH * HD];   // (B,S,KV,HD)
__device__ float g_o[(size_t)BB * SS * HH  * HD];   // (B,S,H,HD)

// ---------------- PTX helpers ----------------
__device__ __forceinline__ uint32_t smaddr(const void* p) {
    return (uint32_t)__cvta_generic_to_shared(p);
}
__device__ __forceinline__ void ldsm_x4(uint32_t* r, uint32_t addr) {
    asm volatile("ldmatrix.sync.aligned.m8n8.x4.shared.b16 {%0,%1,%2,%3}, [%4];"
        : "=r"(r[0]), "=r"(r[1]), "=r"(r[2]), "=r"(r[3]) : "r"(addr));
}
__device__ __forceinline__ void ldsm_x2(uint32_t* r, uint32_t addr) {
    asm volatile("ldmatrix.sync.aligned.m8n8.x2.shared.b16 {%0,%1}, [%2];"
        : "=r"(r[0]), "=r"(r[1]) : "r"(addr));
}
__device__ __forceinline__ void ldsm_x2t(uint32_t* r, uint32_t addr) {
    asm volatile("ldmatrix.sync.aligned.m8n8.x2.trans.shared.b16 {%0,%1}, [%2];"
        : "=r"(r[0]), "=r"(r[1]) : "r"(addr));
}
__device__ __forceinline__ void mma_bf16(float* c, const uint32_t* a, const uint32_t* b) {
    asm volatile(
        "mma.sync.aligned.m16n8k16.row.col.f32.bf16.bf16.f32 "
        "{%0,%1,%2,%3}, {%4,%5,%6,%7}, {%8,%9}, {%0,%1,%2,%3};"
        : "+f"(c[0]), "+f"(c[1]), "+f"(c[2]), "+f"(c[3])
        : "r"(a[0]), "r"(a[1]), "r"(a[2]), "r"(a[3]), "r"(b[0]), "r"(b[1]));
}
__device__ __forceinline__ void split_store(float4 v, bf16* hi, bf16* lo) {
    bf162 H0 = __floats2bfloat162_rn(v.x, v.y);
    bf162 H1 = __floats2bfloat162_rn(v.z, v.w);
    bf162 L0 = __floats2bfloat162_rn(v.x - __low2float(H0), v.y - __high2float(H0));
    bf162 L1 = __floats2bfloat162_rn(v.z - __low2float(H1), v.w - __high2float(H1));
    *(bf162*)hi       = H0;
    *(bf162*)(hi + 2) = H1;
    *(bf162*)lo       = L0;
    *(bf162*)(lo + 2) = L1;
}

// ---------------------------------------------------------------------------
// bf16x3 split GEMM core (unchanged best core) — used by qkv / wo / av.
// ---------------------------------------------------------------------------
#define AROW 40
#define BROWN 136

template<bool BTRANS>
__device__ __forceinline__ void gemm_core(
    const float* __restrict__ A, int lda,
    const float* __restrict__ B, int ldb,
    float* __restrict__ C, int ldc, int K, float alpha)
{
    __shared__ __align__(16) __nv_bfloat16 sAh[128 * AROW];
    __shared__ __align__(16) __nv_bfloat16 sAl[128 * AROW];
    __shared__ __align__(16) __nv_bfloat16 sBh[5120];
    __shared__ __align__(16) __nv_bfloat16 sBl[5120];

    const int tid  = threadIdx.x;
    const int lane = tid & 31;
    const int wid  = tid >> 5;
    const int wm   = (wid >> 2) << 6;   // 0 or 64
    const int wn   = (wid & 3) << 5;    // 0,32,64,96

    float acc[4][4][4];
#pragma unroll
    for (int i = 0; i < 4; ++i)
#pragma unroll
        for (int j = 0; j < 4; ++j)
#pragma unroll
            for (int l = 0; l < 4; ++l) acc[i][j][l] = 0.f;

    for (int k0 = 0; k0 < K; k0 += 32) {
        {
            int r = tid >> 3;
            const int c = (tid & 7) << 2;
#pragma unroll
            for (int p = 0; p < 4; ++p, r += 32) {
                float4 v = *(const float4*)(A + (size_t)r * lda + k0 + c);
                split_store(v, &sAh[r * AROW + c], &sAl[r * AROW + c]);
            }
        }
        if (BTRANS) {
            int r = tid >> 3;
            const int c = (tid & 7) << 2;
#pragma unroll
            for (int p = 0; p < 4; ++p, r += 32) {
                float4 v = *(const float4*)(B + (size_t)r * ldb + k0 + c);
                split_store(v, &sBh[r * AROW + c], &sBl[r * AROW + c]);
            }
        } else {
            int r = tid >> 5;
            const int c = (tid & 31) << 2;
#pragma unroll
            for (int p = 0; p < 4; ++p, r += 8) {
                float4 v = *(const float4*)(B + (size_t)(k0 + r) * ldb + c);
                split_store(v, &sBh[r * BROWN + c], &sBl[r * BROWN + c]);
            }
        }
        __syncthreads();

#pragma unroll
        for (int ks = 0; ks < 2; ++ks) {
            uint32_t af[4][4];
            uint32_t bh[4][2];
            uint32_t bl[4][2];

            const int arow_off = (lane & 15);
            const int akb = ks * 32 + ((lane >> 4) << 4);

#pragma unroll
            for (int mt = 0; mt < 4; ++mt)
                ldsm_x4(af[mt], smaddr(&sAh[(wm + mt * 16 + arow_off) * AROW]) + akb);

#pragma unroll
            for (int nt = 0; nt < 4; ++nt) {
                if (BTRANS) {
                    uint32_t ad = smaddr(&sBh[(wn + nt * 8 + (lane & 7)) * AROW])
                                + ks * 32 + (((lane >> 3) & 1) << 4);
                    ldsm_x2(bh[nt], ad);
                } else {
                    uint32_t ad = smaddr(&sBh[(ks * 16 + (lane & 15)) * BROWN + wn + nt * 8]);
                    ldsm_x2t(bh[nt], ad);
                }
            }
#pragma unroll
            for (int mt = 0; mt < 4; ++mt)
#pragma unroll
                for (int nt = 0; nt < 4; ++nt)
                    mma_bf16(acc[mt][nt], af[mt], bh[nt]);

#pragma unroll
            for (int nt = 0; nt < 4; ++nt) {
                if (BTRANS) {
                    uint32_t ad = smaddr(&sBl[(wn + nt * 8 + (lane & 7)) * AROW])
                                + ks * 32 + (((lane >> 3) & 1) << 4);
                    ldsm_x2(bl[nt], ad);
                } else {
                    uint32_t ad = smaddr(&sBl[(ks * 16 + (lane & 15)) * BROWN + wn + nt * 8]);
                    ldsm_x2t(bl[nt], ad);
                }
            }
#pragma unroll
            for (int mt = 0; mt < 4; ++mt)
#pragma unroll
                for (int nt = 0; nt < 4; ++nt)
                    mma_bf16(acc[mt][nt], af[mt], bl[nt]);

#pragma unroll
            for (int mt = 0; mt < 4; ++mt)
                ldsm_x4(af[mt], smaddr(&sAl[(wm + mt * 16 + arow_off) * AROW]) + akb);
#pragma unroll
            for (int mt = 0; mt < 4; ++mt)
#pragma unroll
                for (int nt = 0; nt < 4; ++nt)
                    mma_bf16(acc[mt][nt], af[mt], bh[nt]);
        }
        __syncthreads();
    }

#pragma unroll
    for (int mt = 0; mt < 4; ++mt) {
#pragma unroll
        for (int nt = 0; nt < 4; ++nt) {
            int r = wm + mt * 16 + (lane >> 2);
            int c = wn + nt * 8 + ((lane & 3) << 1);
            float2 v0 = make_float2(alpha * acc[mt][nt][0], alpha * acc[mt][nt][1]);
            float2 v1 = make_float2(alpha * acc[mt][nt][2], alpha * acc[mt][nt][3]);
            *(float2*)&C[(size_t)r * ldc + c]       = v0;
            *(float2*)&C[(size_t)(r + 8) * ldc + c] = v1;
        }
    }
}

// ---------------------------------------------------------------------------
// Fused QKV projection
// ---------------------------------------------------------------------------
__global__ __launch_bounds__(256, 2) void qkv_mma(
    const float* __restrict__ x,
    const float* __restrict__ wq, const float* __restrict__ wk,
    const float* __restrict__ wv,
    float* __restrict__ q, float* __restrict__ k, float* __restrict__ v)
{
    const int n0 = blockIdx.x * 128;
    const float* A = x + (size_t)blockIdx.y * 128 * DD;

    if (n0 < HH * HD) {
        const float* B = wq + (size_t)n0 * DD;
        float* C = q + (size_t)blockIdx.y * 128 * (HH * HD) + n0;
        gemm_core<true>(A, DD, B, DD, C, HH * HD, DD, 1.0f);
    } else if (n0 < HH * HD + KVH * HD) {
        const int m = n0 - HH * HD;
        const float* B = wk + (size_t)m * DD;
        float* C = k + (size_t)blockIdx.y * 128 * (KVH * HD) + m;
        gemm_core<true>(A, DD, B, DD, C, KVH * HD, DD, 1.0f);
    } else {
        const int m = n0 - HH * HD - KVH * HD;
        const float* B = wv + (size_t)m * DD;
        float* C = v + (size_t)blockIdx.y * 128 * (KVH * HD) + m;
        gemm_core<true>(A, DD, B, DD, C, KVH * HD, DD, 1.0f);
    }
}

__global__ __launch_bounds__(256, 2) void proj_mma(
    int K, const float* __restrict__ A, int lda,
    const float* __restrict__ B, int ldb, float* __restrict__ C, int ldc)
{
    const float* Ab = A + (size_t)blockIdx.y * 128 * lda;
    const float* Bb = B + (size_t)blockIdx.x * 128 * ldb;
    float* Cb = C + (size_t)blockIdx.y * 128 * ldc + (size_t)blockIdx.x * 128;
    gemm_core<true>(Ab, lda, Bb, ldb, Cb, ldc, K, 1.0f);
}

// ---------------------------------------------------------------------------
// GQA-paired score, fully-staged: K tile + BOTH heads' Q tiles staged once
// into 204KB dynamic smem (1 CTA/SM), ONE sync, then barrier-free mainloop.
// ---------------------------------------------------------------------------
#define KROW 136
#define SCORE_DSM (6 * 128 * KROW * 2)   // 208896 B

__global__ __launch_bounds__(256, 1) void score_pair(
    const float* __restrict__ q, const float* __restrict__ k,
    float* __restrict__ attn)
{
    extern __shared__ __align__(16) bf16 dyn[];
    bf16* sBh = dyn;
    bf16* sBl = dyn + 128 * KROW;
    bf16* sQh[2] = { dyn + 2 * 128 * KROW, dyn + 4 * 128 * KROW };
    bf16* sQl[2] = { dyn + 3 * 128 * KROW, dyn + 5 * 128 * KROW };

    const int x = blockIdx.x, y = blockIdx.y;
    const int bkv = blockIdx.z;
    const int b = bkv / KVH, kv = bkv % KVH;
    const int h0 = kv * GG;

    const int tid  = threadIdx.x;
    const int lane = tid & 31;
    const int wid  = tid >> 5;
    const int wm   = (wid >> 2) << 6;
    const int wn   = (wid & 3) << 5;

    if (x > y) {
        const float4 z = make_float4(0.f, 0.f, 0.f, 0.f);
#pragma unroll
        for (int g = 0; g < GG; ++g) {
            float* C = attn + ((size_t)(b * HH + h0 + g)) * SS * SS
                     + (size_t)y * 128 * SS + (size_t)x * 128;
            for (int t = tid; t < 128 * 32; t += 256) {
                int r = t >> 5, c = (t & 31) << 2;
                *(float4*)&C[(size_t)r * SS + c] = z;
            }
        }
        return;
    }

    // stage K tile (shared by both heads)
    {
        const float* B = k + ((size_t)b * SS * KVH + kv) * HD
                           + (size_t)x * 128 * (KVH * HD);
        const int ldb = KVH * HD;
        for (int t = tid; t < 128 * 32; t += 256) {
            int r = t >> 5, c = (t & 31) << 2;
            float4 v = *(const float4*)(B + (size_t)r * ldb + c);
            split_store(v, &sBh[r * KROW + c], &sBl[r * KROW + c]);
        }
    }
    // stage both Q tiles
#pragma unroll
    for (int g = 0; g < GG; ++g) {
        const float* A = q + ((size_t)b * SS * HH + h0 + g) * HD
                           + (size_t)y * 128 * (HH * HD);
        const int lda = HH * HD;
        for (int t = tid; t < 128 * 32; t += 256) {
            int r = t >> 5, c = (t & 31) << 2;
            float4 v = *(const float4*)(A + (size_t)r * lda + c);
            split_store(v, &sQh[g][r * KROW + c], &sQl[g][r * KROW + c]);
        }
    }
    __syncthreads();

    for (int g = 0; g < GG; ++g) {
        const bf16* pAh = sQh[g];
        const bf16* pAl = sQl[g];
        float* C = attn + ((size_t)(b * HH + h0 + g)) * SS * SS
                 + (size_t)y * 128 * SS + (size_t)x * 128;

        float acc[4][4][4];
#pragma unroll
        for (int i = 0; i < 4; ++i)
#pragma unroll
            for (int j = 0; j < 4; ++j)
#pragma unroll
                for (int l = 0; l < 4; ++l) acc[i][j][l] = 0.f;

#pragma unroll 4
        for (int ks8 = 0; ks8 < 8; ++ks8) {
            uint32_t af[4][4], bh[4][2], bl[4][2];
            const int arow_off = (lane & 15);
            const int akb = ks8 * 32 + ((lane >> 4) << 4);
            const int bkb = ks8 * 32 + (((lane >> 3) & 1) << 4);

#pragma unroll
            for (int mt = 0; mt < 4; ++mt)
                ldsm_x4(af[mt], smaddr(&pAh[(wm + mt * 16 + arow_off) * KROW]) + akb);
#pragma unroll
            for (int nt = 0; nt < 4; ++nt)
                ldsm_x2(bh[nt], smaddr(&sBh[(wn + nt * 8 + (lane & 7)) * KROW]) + bkb);
#pragma unroll
            for (int mt = 0; mt < 4; ++mt)
#pragma unroll
                for (int nt = 0; nt < 4; ++nt) mma_bf16(acc[mt][nt], af[mt], bh[nt]);

#pragma unroll
            for (int nt = 0; nt < 4; ++nt)
                ldsm_x2(bl[nt], smaddr(&sBl[(wn + nt * 8 + (lane & 7)) * KROW]) + bkb);
#pragma unroll
            for (int mt = 0; mt < 4; ++mt)
#pragma unroll
                for (int nt = 0; nt < 4; ++nt) mma_bf16(acc[mt][nt], af[mt], bl[nt]);

#pragma unroll
            for (int mt = 0; mt < 4; ++mt)
                ldsm_x4(af[mt], smaddr(&pAl[(wm + mt * 16 + arow_off) * KROW]) + akb);
#pragma unroll
            for (int mt = 0; mt < 4; ++mt)
#pragma unroll
                for (int nt = 0; nt < 4; ++nt) mma_bf16(acc[mt][nt], af[mt], bh[nt]);
        }

#pragma unroll
        for (int mt = 0; mt < 4; ++mt) {
#pragma unroll
            for (int nt = 0; nt < 4; ++nt) {
                int r = wm + mt * 16 + (lane >> 2);
                int c = wn + nt * 8 + ((lane & 3) << 1);
                float2 v0 = make_float2(SCALE * acc[mt][nt][0], SCALE * acc[mt][nt][1]);
                float2 v1 = make_float2(SCALE * acc[mt][nt][2], SCALE * acc[mt][nt][3]);
                *(float2*)&C[(size_t)r * SS + c]       = v0;
                *(float2*)&C[(size_t)(r + 8) * SS + c] = v1;
            }
        }
    }
}

// AV (NN core + heavy-first scheduling)
__global__ __launch_bounds__(256, 2) void av_mma(
    const float* __restrict__ attn, const float* __restrict__ v,
    float* __restrict__ o)
{
    const int ry = 15 - (int)blockIdx.y;       // heavy first (LPT)
    const int bh = blockIdx.z;
    const int h = bh % HH, b = bh / HH, kv = h / GG;
    const float* A = attn + (size_t)bh * SS * SS + (size_t)ry * 128 * SS;
    const float* B = v + ((size_t)b * SS * KVH + kv) * HD;
    float* C = o + ((size_t)b * SS * HH + h) * HD
                 + (size_t)ry * 128 * (HH * HD);
    const int K = (ry + 1) * 128;
    gemm_core<false>(A, SS, B, KVH * HD, C, HH * HD, K, 1.0f);
}

// ---------------------------------------------------------------------------
// Fused RMSNorm + RoPE for BOTH Q and K in one launch (R10-validated).
// ---------------------------------------------------------------------------
__global__ __launch_bounds__(128) void normrope_all(
    float* __restrict__ qd, float* __restrict__ kd,
    const float* __restrict__ qw, const float* __restrict__ kw,
    const float* __restrict__ cosb, const float* __restrict__ sinb)
{
    const int HT = HH + KVH;   // 24
    const int idx = blockIdx.x;
    const int hh = idx % HT;
    const int s = (idx / HT) % SS;
    const int b = idx / (HT * SS);
    const int t = threadIdx.x;

    float* ptr;
    const float* w;
    if (hh < HH) { ptr = qd + (((size_t)b * SS + s) * HH + hh) * HD; w = qw; }
    else         { ptr = kd + (((size_t)b * SS + s) * KVH + (hh - HH)) * HD; w = kw; }

    float v = ptr[t];
    float ss = v * v;
#pragma unroll
    for (int o = 16; o; o >>= 1) ss += __shfl_xor_sync(0xffffffffu, ss, o);

    __shared__ float ws[4];
    __shared__ float sh[128];
    const int lane = t & 31, wid = t >> 5;
    if (lane == 0) ws[wid] = ss;
    __syncthreads();
    float var = (ws[0] + ws[1] + ws[2] + ws[3]) * (1.0f / HD);
    float xn = v * rsqrtf(var + 1e-6f) * w[t];
    sh[t] = xn;
    __syncthreads();
    float rot = (t < 64) ? -sh[t + 64] : sh[t - 64];

    const float* cp = cosb + ((size_t)b * SS + s) * HD;
    const float* sp = sinb + ((size_t)b * SS + s) * HD;
    ptr[t] = xn * cp[t] + rot * sp[t];
}

// ---------------------------------------------------------------------------
// Row softmax (causal). Span-only writes, warp-shuffle reductions, __expf.
// ---------------------------------------------------------------------------
__global__ __launch_bounds__(256) void softmax_kernel(float* __restrict__ attn)
{
    __shared__ float buf[SS];
    __shared__ float redm[8];
    __shared__ float reds[8];
    const int row = blockIdx.x;
    const int qi = row & (SS - 1);
    const int valid = qi + 1;
    const int span = ((qi >> 7) + 1) << 7;
    float* base = attn + (size_t)row * SS;
    const int tid = threadIdx.x;
    const int lane = tid & 31, wrp = tid >> 5;

    float m = -1e30f;
    for (int t = tid * 4; t < span; t += 1024) {
        float4 v = *(const float4*)(base + t);
        v.x = (t + 0 < valid) ? v.x : -1e30f;
        v.y = (t + 1 < valid) ? v.y : -1e30f;
        v.z = (t + 2 < valid) ? v.z : -1e30f;
        v.w = (t + 3 < valid) ? v.w : -1e30f;
        *(float4*)(buf + t) = v;
        m = fmaxf(m, fmaxf(fmaxf(v.x, v.y), fmaxf(v.z, v.w)));
    }
#pragma unroll
    for (int o = 16; o; o >>= 1) m = fmaxf(m, __shfl_xor_sync(0xffffffffu, m, o));
    if (lane == 0) redm[wrp] = m;
    __syncthreads();
    float mx = redm[0];
#pragma unroll
    for (int i = 1; i < 8; ++i) mx = fmaxf(mx, redm[i]);

    float sum = 0.f;
    for (int t = tid * 4; t < span; t += 1024) {
        float4 v = *(const float4*)(buf + t);
        v.x = __expf(v.x - mx); v.y = __expf(v.y - mx);
        v.z = __expf(v.z - mx); v.w = __expf(v.w - mx);
        *(float4*)(buf + t) = v;
        sum += v.x + v.y + v.z + v.w;
    }
#pragma unroll
    for (int o = 16; o; o >>= 1) sum += __shfl_xor_sync(0xffffffffu, sum, o);
    if (lane == 0) reds[wrp] = sum;
    __syncthreads();
    float tot = reds[0] + reds[1] + reds[2] + reds[3]
              + reds[4] + reds[5] + reds[6] + reds[7];
    const float inv = 1.0f / tot;

    for (int t = tid * 4; t < span; t += 1024) {
        float4 v = *(const float4*)(buf + t);
        v.x *= inv; v.y *= inv; v.z *= inv; v.w *= inv;
        *(float4*)(base + t) = v;
    }
}

// ---------------- launch ----------------
extern "C" void kernel_launch(void* const* d_in, const int* in_sizes, int n_in,
                              void* d_out, int out_size)
{
    const float* x    = (const float*)d_in[0];
    const float* cosb = (const float*)d_in[1];
    const float* sinb = (const float*)d_in[2];
    // d_in[3] = attention_mask (pure causal; applied analytically)
    const float* wq   = (const float*)d_in[4];
    const float* wk   = (const float*)d_in[5];
    const float* wv   = (const float*)d_in[6];
    const float* wo   = (const float*)d_in[7];
    const float* qw   = (const float*)d_in[8];
    const float* kw   = (const float*)d_in[9];

    float* out  = (float*)d_out;                    // (B,S,H*HD)
    float* attn = out + (size_t)BB * SS * HH * HD;  // (B,H,S,S)

    float *pq, *pk, *pv, *po;
    cudaGetSymbolAddress((void**)&pq, g_q);
    cudaGetSymbolAddress((void**)&pk, g_k);
    cudaGetSymbolAddress((void**)&pv, g_v);
    cudaGetSymbolAddress((void**)&po, g_o);

    cudaFuncSetAttribute(score_pair,
                         cudaFuncAttributeMaxDynamicSharedMemorySize, SCORE_DSM);

    const int BS = BB * SS;   // 4096
    dim3 blk(256);

    // Fused QKV projection
    qkv_mma<<<dim3(32, BS / 128), blk>>>(x, wq, wk, wv, pq, pk, pv);

    // RMSNorm + RoPE (Q and K, single launch)
    normrope_all<<<BB * SS * (HH + KVH), 128>>>(pq, pk, qw, kw, cosb, sinb);

    // Scores: GQA-paired, fully staged, barrier-free mainloop
    score_pair<<<dim3(SS / 128, SS / 128, BB * KVH), blk, SCORE_DSM>>>(pq, pk, attn);

    // Softmax (span-only), AV (heavy-first)
    softmax_kernel<<<BB * HH * SS, 256>>>(attn);
    av_mma<<<dim3(1, 16, BB * HH), blk>>>(attn, pv, po);

    // Output projection
    proj_mma<<<dim3(DD / 128, BS / 128), blk>>>(
        HH * HD, po, HH * HD, wo, HH * HD, out, DD);
}

// round 15
// speedup vs baseline: 1.0505x; 1.0505x over previous
#include <cuda_runtime.h>
#include <cuda_bf16.h>
#include <math.h>
#include <stdint.h>

#define BB   2
#define SS   2048
#define DD   2048
#define HH   16
#define KVH  8
#define GG   2
#define HD   128
#define SCALE 0.08838834764831845f

typedef __nv_bfloat16 bf16;
typedef __nv_bfloat162 bf162;

// ---------------- persistent scratch ----------------
__device__ float g_q[(size_t)BB * SS * HH  * HD];   // (B,S,H,HD)
__device__ float g_k[(size_t)BB * SS * KVH * HD];   // (B,S,KV,HD)
__device__ float g_v[(size_t)BB * SS * KVH * HD];   // (B,S,KV,HD)
__device__ float g_o[(size_t)BB * SS * HH  * HD];   // (B,S,H,HD)

// ---------------- PTX helpers ----------------
__device__ __forceinline__ uint32_t smaddr(const void* p) {
    return (uint32_t)__cvta_generic_to_shared(p);
}
__device__ __forceinline__ void ldsm_x4(uint32_t* r, uint32_t addr) {
    asm volatile("ldmatrix.sync.aligned.m8n8.x4.shared.b16 {%0,%1,%2,%3}, [%4];"
        : "=r"(r[0]), "=r"(r[1]), "=r"(r[2]), "=r"(r[3]) : "r"(addr));
}
__device__ __forceinline__ void ldsm_x2(uint32_t* r, uint32_t addr) {
    asm volatile("ldmatrix.sync.aligned.m8n8.x2.shared.b16 {%0,%1}, [%2];"
        : "=r"(r[0]), "=r"(r[1]) : "r"(addr));
}
__device__ __forceinline__ void ldsm_x2t(uint32_t* r, uint32_t addr) {
    asm volatile("ldmatrix.sync.aligned.m8n8.x2.trans.shared.b16 {%0,%1}, [%2];"
        : "=r"(r[0]), "=r"(r[1]) : "r"(addr));
}
__device__ __forceinline__ void mma_bf16(float* c, const uint32_t* a, const uint32_t* b) {
    asm volatile(
        "mma.sync.aligned.m16n8k16.row.col.f32.bf16.bf16.f32 "
        "{%0,%1,%2,%3}, {%4,%5,%6,%7}, {%8,%9}, {%0,%1,%2,%3};"
        : "+f"(c[0]), "+f"(c[1]), "+f"(c[2]), "+f"(c[3])
        : "r"(a[0]), "r"(a[1]), "r"(a[2]), "r"(a[3]), "r"(b[0]), "r"(b[1]));
}
__device__ __forceinline__ void split_store(float4 v, bf16* hi, bf16* lo) {
    bf162 H0 = __floats2bfloat162_rn(v.x, v.y);
    bf162 H1 = __floats2bfloat162_rn(v.z, v.w);
    bf162 L0 = __floats2bfloat162_rn(v.x - __low2float(H0), v.y - __high2float(H0));
    bf162 L1 = __floats2bfloat162_rn(v.z - __low2float(H1), v.w - __high2float(H1));
    *(bf162*)hi       = H0;
    *(bf162*)(hi + 2) = H1;
    *(bf162*)lo       = L0;
    *(bf162*)(lo + 2) = L1;
}

// ---------------------------------------------------------------------------
// bf16x3 split GEMM core (unchanged best core) — used by qkv / wo / av.
// ---------------------------------------------------------------------------
#define AROW 40
#define BROWN 136

template<bool BTRANS>
__device__ __forceinline__ void gemm_core(
    const float* __restrict__ A, int lda,
    const float* __restrict__ B, int ldb,
    float* __restrict__ C, int ldc, int K, float alpha)
{
    __shared__ __align__(16) __nv_bfloat16 sAh[128 * AROW];
    __shared__ __align__(16) __nv_bfloat16 sAl[128 * AROW];
    __shared__ __align__(16) __nv_bfloat16 sBh[5120];
    __shared__ __align__(16) __nv_bfloat16 sBl[5120];

    const int tid  = threadIdx.x;
    const int lane = tid & 31;
    const int wid  = tid >> 5;
    const int wm   = (wid >> 2) << 6;   // 0 or 64
    const int wn   = (wid & 3) << 5;    // 0,32,64,96

    float acc[4][4][4];
#pragma unroll
    for (int i = 0; i < 4; ++i)
#pragma unroll
        for (int j = 0; j < 4; ++j)
#pragma unroll
            for (int l = 0; l < 4; ++l) acc[i][j][l] = 0.f;

    for (int k0 = 0; k0 < K; k0 += 32) {
        {
            int r = tid >> 3;
            const int c = (tid & 7) << 2;
#pragma unroll
            for (int p = 0; p < 4; ++p, r += 32) {
                float4 v = *(const float4*)(A + (size_t)r * lda + k0 + c);
                split_store(v, &sAh[r * AROW + c], &sAl[r * AROW + c]);
            }
        }
        if (BTRANS) {
            int r = tid >> 3;
            const int c = (tid & 7) << 2;
#pragma unroll
            for (int p = 0; p < 4; ++p, r += 32) {
                float4 v = *(const float4*)(B + (size_t)r * ldb + k0 + c);
                split_store(v, &sBh[r * AROW + c], &sBl[r * AROW + c]);
            }
        } else {
            int r = tid >> 5;
            const int c = (tid & 31) << 2;
#pragma unroll
            for (int p = 0; p < 4; ++p, r += 8) {
                float4 v = *(const float4*)(B + (size_t)(k0 + r) * ldb + c);
                split_store(v, &sBh[r * BROWN + c], &sBl[r * BROWN + c]);
            }
        }
        __syncthreads();

#pragma unroll
        for (int ks = 0; ks < 2; ++ks) {
            uint32_t af[4][4];
            uint32_t bh[4][2];
            uint32_t bl[4][2];

            const int arow_off = (lane & 15);
            const int akb = ks * 32 + ((lane >> 4) << 4);

#pragma unroll
            for (int mt = 0; mt < 4; ++mt)
                ldsm_x4(af[mt], smaddr(&sAh[(wm + mt * 16 + arow_off) * AROW]) + akb);

#pragma unroll
            for (int nt = 0; nt < 4; ++nt) {
                if (BTRANS) {
                    uint32_t ad = smaddr(&sBh[(wn + nt * 8 + (lane & 7)) * AROW])
                                + ks * 32 + (((lane >> 3) & 1) << 4);
                    ldsm_x2(bh[nt], ad);
                } else {
                    uint32_t ad = smaddr(&sBh[(ks * 16 + (lane & 15)) * BROWN + wn + nt * 8]);
                    ldsm_x2t(bh[nt], ad);
                }
            }
#pragma unroll
            for (int mt = 0; mt < 4; ++mt)
#pragma unroll
                for (int nt = 0; nt < 4; ++nt)
                    mma_bf16(acc[mt][nt], af[mt], bh[nt]);

#pragma unroll
            for (int nt = 0; nt < 4; ++nt) {
                if (BTRANS) {
                    uint32_t ad = smaddr(&sBl[(wn + nt * 8 + (lane & 7)) * AROW])
                                + ks * 32 + (((lane >> 3) & 1) << 4);
                    ldsm_x2(bl[nt], ad);
                } else {
                    uint32_t ad = smaddr(&sBl[(ks * 16 + (lane & 15)) * BROWN + wn + nt * 8]);
                    ldsm_x2t(bl[nt], ad);
                }
            }
#pragma unroll
            for (int mt = 0; mt < 4; ++mt)
#pragma unroll
                for (int nt = 0; nt < 4; ++nt)
                    mma_bf16(acc[mt][nt], af[mt], bl[nt]);

#pragma unroll
            for (int mt = 0; mt < 4; ++mt)
                ldsm_x4(af[mt], smaddr(&sAl[(wm + mt * 16 + arow_off) * AROW]) + akb);
#pragma unroll
            for (int mt = 0; mt < 4; ++mt)
#pragma unroll
                for (int nt = 0; nt < 4; ++nt)
                    mma_bf16(acc[mt][nt], af[mt], bh[nt]);
        }
        __syncthreads();
    }

#pragma unroll
    for (int mt = 0; mt < 4; ++mt) {
#pragma unroll
        for (int nt = 0; nt < 4; ++nt) {
            int r = wm + mt * 16 + (lane >> 2);
            int c = wn + nt * 8 + ((lane & 3) << 1);
            float2 v0 = make_float2(alpha * acc[mt][nt][0], alpha * acc[mt][nt][1]);
            float2 v1 = make_float2(alpha * acc[mt][nt][2], alpha * acc[mt][nt][3]);
            *(float2*)&C[(size_t)r * ldc + c]       = v0;
            *(float2*)&C[(size_t)(r + 8) * ldc + c] = v1;
        }
    }
}

// ---------------------------------------------------------------------------
// Fused QKV projection
// ---------------------------------------------------------------------------
__global__ __launch_bounds__(256, 2) void qkv_mma(
    const float* __restrict__ x,
    const float* __restrict__ wq, const float* __restrict__ wk,
    const float* __restrict__ wv,
    float* __restrict__ q, float* __restrict__ k, float* __restrict__ v)
{
    const int n0 = blockIdx.x * 128;
    const float* A = x + (size_t)blockIdx.y * 128 * DD;

    if (n0 < HH * HD) {
        const float* B = wq + (size_t)n0 * DD;
        float* C = q + (size_t)blockIdx.y * 128 * (HH * HD) + n0;
        gemm_core<true>(A, DD, B, DD, C, HH * HD, DD, 1.0f);
    } else if (n0 < HH * HD + KVH * HD) {
        const int m = n0 - HH * HD;
        const float* B = wk + (size_t)m * DD;
        float* C = k + (size_t)blockIdx.y * 128 * (KVH * HD) + m;
        gemm_core<true>(A, DD, B, DD, C, KVH * HD, DD, 1.0f);
    } else {
        const int m = n0 - HH * HD - KVH * HD;
        const float* B = wv + (size_t)m * DD;
        float* C = v + (size_t)blockIdx.y * 128 * (KVH * HD) + m;
        gemm_core<true>(A, DD, B, DD, C, KVH * HD, DD, 1.0f);
    }
}

__global__ __launch_bounds__(256, 2) void proj_mma(
    int K, const float* __restrict__ A, int lda,
    const float* __restrict__ B, int ldb, float* __restrict__ C, int ldc)
{
    const float* Ab = A + (size_t)blockIdx.y * 128 * lda;
    const float* Bb = B + (size_t)blockIdx.x * 128 * ldb;
    float* Cb = C + (size_t)blockIdx.y * 128 * ldc + (size_t)blockIdx.x * 128;
    gemm_core<true>(Ab, lda, Bb, ldb, Cb, ldc, K, 1.0f);
}

// ---------------------------------------------------------------------------
// GQA-paired score kernel (R13 version, 2 CTAs/SM): K tile staged once in
// 68KB dynamic smem; Q chunks staged per head.
// ---------------------------------------------------------------------------
#define KROW 136
#define SCORE_DSM (2 * 128 * KROW * 2)   // 69632 B

__global__ __launch_bounds__(256, 2) void score_pair(
    const float* __restrict__ q, const float* __restrict__ k,
    float* __restrict__ attn)
{
    extern __shared__ __align__(16) bf16 dyn[];
    bf16* sBh = dyn;
    bf16* sBl = dyn + 128 * KROW;
    __shared__ __align__(16) bf16 sAh[128 * AROW];
    __shared__ __align__(16) bf16 sAl[128 * AROW];

    const int x = blockIdx.x, y = blockIdx.y;
    const int bkv = blockIdx.z;
    const int b = bkv / KVH, kv = bkv % KVH;
    const int h0 = kv * GG;

    const int tid  = threadIdx.x;
    const int lane = tid & 31;
    const int wid  = tid >> 5;
    const int wm   = (wid >> 2) << 6;
    const int wn   = (wid & 3) << 5;

    if (x > y) {
        const float4 z = make_float4(0.f, 0.f, 0.f, 0.f);
#pragma unroll
        for (int g = 0; g < GG; ++g) {
            float* C = attn + ((size_t)(b * HH + h0 + g)) * SS * SS
                     + (size_t)y * 128 * SS + (size_t)x * 128;
            for (int t = tid; t < 128 * 32; t += 256) {
                int r = t >> 5, c = (t & 31) << 2;
                *(float4*)&C[(size_t)r * SS + c] = z;
            }
        }
        return;
    }

    // stage FULL K tile (128 rows x 128 K) once, hi/lo split
    const float* B = k + ((size_t)b * SS * KVH + kv) * HD
                       + (size_t)x * 128 * (KVH * HD);
    const int ldb = KVH * HD;
    for (int t = tid; t < 128 * 32; t += 256) {
        int r = t >> 5, c = (t & 31) << 2;
        float4 v = *(const float4*)(B + (size_t)r * ldb + c);
        split_store(v, &sBh[r * KROW + c], &sBl[r * KROW + c]);
    }
    __syncthreads();

#pragma unroll
    for (int g = 0; g < GG; ++g) {
        const float* A = q + ((size_t)b * SS * HH + h0 + g) * HD
                           + (size_t)y * 128 * (HH * HD);
        float* C = attn + ((size_t)(b * HH + h0 + g)) * SS * SS
                 + (size_t)y * 128 * SS + (size_t)x * 128;
        const int lda = HH * HD;

        float acc[4][4][4];
#pragma unroll
        for (int i = 0; i < 4; ++i)
#pragma unroll
            for (int j = 0; j < 4; ++j)
#pragma unroll
                for (int l = 0; l < 4; ++l) acc[i][j][l] = 0.f;

#pragma unroll
        for (int ch = 0; ch < 4; ++ch) {
            {
                int r = tid >> 3;
                const int c = (tid & 7) << 2;
#pragma unroll
                for (int p = 0; p < 4; ++p, r += 32) {
                    float4 v = *(const float4*)(A + (size_t)r * lda + ch * 32 + c);
                    split_store(v, &sAh[r * AROW + c], &sAl[r * AROW + c]);
                }
            }
            __syncthreads();

#pragma unroll
            for (int ks = 0; ks < 2; ++ks) {
                uint32_t af[4][4], bh[4][2], bl[4][2];
                const int arow_off = (lane & 15);
                const int akb = ks * 32 + ((lane >> 4) << 4);
                const int bkb = ch * 64 + ks * 32 + (((lane >> 3) & 1) << 4);

#pragma unroll
                for (int mt = 0; mt < 4; ++mt)
                    ldsm_x4(af[mt], smaddr(&sAh[(wm + mt * 16 + arow_off) * AROW]) + akb);
#pragma unroll
                for (int nt = 0; nt < 4; ++nt)
                    ldsm_x2(bh[nt], smaddr(&sBh[(wn + nt * 8 + (lane & 7)) * KROW]) + bkb);
#pragma unroll
                for (int mt = 0; mt < 4; ++mt)
#pragma unroll
                    for (int nt = 0; nt < 4; ++nt) mma_bf16(acc[mt][nt], af[mt], bh[nt]);

#pragma unroll
                for (int nt = 0; nt < 4; ++nt)
                    ldsm_x2(bl[nt], smaddr(&sBl[(wn + nt * 8 + (lane & 7)) * KROW]) + bkb);
#pragma unroll
                for (int mt = 0; mt < 4; ++mt)
#pragma unroll
                    for (int nt = 0; nt < 4; ++nt) mma_bf16(acc[mt][nt], af[mt], bl[nt]);

#pragma unroll
                for (int mt = 0; mt < 4; ++mt)
                    ldsm_x4(af[mt], smaddr(&sAl[(wm + mt * 16 + arow_off) * AROW]) + akb);
#pragma unroll
                for (int mt = 0; mt < 4; ++mt)
#pragma unroll
                    for (int nt = 0; nt < 4; ++nt) mma_bf16(acc[mt][nt], af[mt], bh[nt]);
            }
            __syncthreads();
        }

#pragma unroll
        for (int mt = 0; mt < 4; ++mt) {
#pragma unroll
            for (int nt = 0; nt < 4; ++nt) {
                int r = wm + mt * 16 + (lane >> 2);
                int c = wn + nt * 8 + ((lane & 3) << 1);
                float2 v0 = make_float2(SCALE * acc[mt][nt][0], SCALE * acc[mt][nt][1]);
                float2 v1 = make_float2(SCALE * acc[mt][nt][2], SCALE * acc[mt][nt][3]);
                *(float2*)&C[(size_t)r * SS + c]       = v0;
                *(float2*)&C[(size_t)(r + 8) * SS + c] = v1;
            }
        }
    }
}

// AV (NN core + heavy-first scheduling)
__global__ __launch_bounds__(256, 2) void av_mma(
    const float* __restrict__ attn, const float* __restrict__ v,
    float* __restrict__ o)
{
    const int ry = 15 - (int)blockIdx.y;       // heavy first (LPT)
    const int bh = blockIdx.z;
    const int h = bh % HH, b = bh / HH, kv = h / GG;
    const float* A = attn + (size_t)bh * SS * SS + (size_t)ry * 128 * SS;
    const float* B = v + ((size_t)b * SS * KVH + kv) * HD;
    float* C = o + ((size_t)b * SS * HH + h) * HD
                 + (size_t)ry * 128 * (HH * HD);
    const int K = (ry + 1) * 128;
    gemm_core<false>(A, SS, B, KVH * HD, C, HH * HD, K, 1.0f);
}

// ---------------------------------------------------------------------------
// Fused RMSNorm + RoPE for BOTH Q and K in one launch.
// ---------------------------------------------------------------------------
__global__ __launch_bounds__(128) void normrope_all(
    float* __restrict__ qd, float* __restrict__ kd,
    const float* __restrict__ qw, const float* __restrict__ kw,
    const float* __restrict__ cosb, const float* __restrict__ sinb)
{
    const int HT = HH + KVH;   // 24
    const int idx = blockIdx.x;
    const int hh = idx % HT;
    const int s = (idx / HT) % SS;
    const int b = idx / (HT * SS);
    const int t = threadIdx.x;

    float* ptr;
    const float* w;
    if (hh < HH) { ptr = qd + (((size_t)b * SS + s) * HH + hh) * HD; w = qw; }
    else         { ptr = kd + (((size_t)b * SS + s) * KVH + (hh - HH)) * HD; w = kw; }

    float v = ptr[t];
    float ss = v * v;
#pragma unroll
    for (int o = 16; o; o >>= 1) ss += __shfl_xor_sync(0xffffffffu, ss, o);

    __shared__ float ws[4];
    __shared__ float sh[128];
    const int lane = t & 31, wid = t >> 5;
    if (lane == 0) ws[wid] = ss;
    __syncthreads();
    float var = (ws[0] + ws[1] + ws[2] + ws[3]) * (1.0f / HD);
    float xn = v * rsqrtf(var + 1e-6f) * w[t];
    sh[t] = xn;
    __syncthreads();
    float rot = (t < 64) ? -sh[t + 64] : sh[t - 64];

    const float* cp = cosb + ((size_t)b * SS + s) * HD;
    const float* sp = sinb + ((size_t)b * SS + s) * HD;
    ptr[t] = xn * cp[t] + rot * sp[t];
}

// ---------------------------------------------------------------------------
// Row softmax (causal). Mask hoisted: bulk loop unmasked, diagonal 128-wide
// tile masked separately. Span-only writes, warp-shuffle reds, __expf.
// ---------------------------------------------------------------------------
__global__ __launch_bounds__(256) void softmax_kernel(float* __restrict__ attn)
{
    __shared__ float buf[SS];
    __shared__ float redm[8];
    __shared__ float reds[8];
    const int row = blockIdx.x;
    const int qi = row & (SS - 1);
    const int valid = qi + 1;
    const int span = ((qi >> 7) + 1) << 7;     // next multiple of 128
    const int dtile = span - 128;              // diagonal tile start
    float* base = attn + (size_t)row * SS;
    const int tid = threadIdx.x;
    const int lane = tid & 31, wrp = tid >> 5;

    float m = -1e30f;
    // bulk: always valid, no mask ALU
    for (int t = tid * 4; t < dtile; t += 1024) {
        float4 v = *(const float4*)(base + t);
        *(float4*)(buf + t) = v;
        m = fmaxf(m, fmaxf(fmaxf(v.x, v.y), fmaxf(v.z, v.w)));
    }
    // diagonal tile: masked (only threads 0..31 hit this, one iter)
    for (int t = dtile + tid * 4; t < span; t += 1024) {
        float4 v = *(const float4*)(base + t);
        v.x = (t + 0 < valid) ? v.x : -1e30f;
        v.y = (t + 1 < valid) ? v.y : -1e30f;
        v.z = (t + 2 < valid) ? v.z : -1e30f;
        v.w = (t + 3 < valid) ? v.w : -1e30f;
        *(float4*)(buf + t) = v;
        m = fmaxf(m, fmaxf(fmaxf(v.x, v.y), fmaxf(v.z, v.w)));
    }
#pragma unroll
    for (int o = 16; o; o >>= 1) m = fmaxf(m, __shfl_xor_sync(0xffffffffu, m, o));
    if (lane == 0) redm[wrp] = m;
    __syncthreads();
    float mx = redm[0];
#pragma unroll
    for (int i = 1; i < 8; ++i) mx = fmaxf(mx, redm[i]);

    float sum = 0.f;
    for (int t = tid * 4; t < span; t += 1024) {
        float4 v = *(const float4*)(buf + t);
        v.x = __expf(v.x - mx); v.y = __expf(v.y - mx);
        v.z = __expf(v.z - mx); v.w = __expf(v.w - mx);
        *(float4*)(buf + t) = v;
        sum += v.x + v.y + v.z + v.w;
    }
#pragma unroll
    for (int o = 16; o; o >>= 1) sum += __shfl_xor_sync(0xffffffffu, sum, o);
    if (lane == 0) reds[wrp] = sum;
    __syncthreads();
    float tot = reds[0] + reds[1] + reds[2] + reds[3]
              + reds[4] + reds[5] + reds[6] + reds[7];
    const float inv = 1.0f / tot;

    for (int t = tid * 4; t < span; t += 1024) {
        float4 v = *(const float4*)(buf + t);
        v.x *= inv; v.y *= inv; v.z *= inv; v.w *= inv;
        *(float4*)(base + t) = v;
    }
}

// ---------------- launch ----------------
extern "C" void kernel_launch(void* const* d_in, const int* in_sizes, int n_in,
                              void* d_out, int out_size)
{
    const float* x    = (const float*)d_in[0];
    const float* cosb = (const float*)d_in[1];
    const float* sinb = (const float*)d_in[2];
    // d_in[3] = attention_mask (pure causal; applied analytically)
    const float* wq   = (const float*)d_in[4];
    const float* wk   = (const float*)d_in[5];
    const float* wv   = (const float*)d_in[6];
    const float* wo   = (const float*)d_in[7];
    const float* qw   = (const float*)d_in[8];
    const float* kw   = (const float*)d_in[9];

    float* out  = (float*)d_out;                    // (B,S,H*HD)
    float* attn = out + (size_t)BB * SS * HH * HD;  // (B,H,S,S)

    float *pq, *pk, *pv, *po;
    cudaGetSymbolAddress((void**)&pq, g_q);
    cudaGetSymbolAddress((void**)&pk, g_k);
    cudaGetSymbolAddress((void**)&pv, g_v);
    cudaGetSymbolAddress((void**)&po, g_o);

    cudaFuncSetAttribute(score_pair,
                         cudaFuncAttributeMaxDynamicSharedMemorySize, SCORE_DSM);

    const int BS = BB * SS;   // 4096
    dim3 blk(256);

    // Fused QKV projection
    qkv_mma<<<dim3(32, BS / 128), blk>>>(x, wq, wk, wv, pq, pk, pv);

    // RMSNorm + RoPE (Q and K, single launch)
    normrope_all<<<BB * SS * (HH + KVH), 128>>>(pq, pk, qw, kw, cosb, sinb);

    // Scores: GQA-paired, K tile staged once per pair; zero tiles included
    score_pair<<<dim3(SS / 128, SS / 128, BB * KVH), blk, SCORE_DSM>>>(pq, pk, attn);

    // Softmax (mask-hoisted, span-only), AV (heavy-first)
    softmax_kernel<<<BB * HH * SS, 256>>>(attn);
    av_mma<<<dim3(1, 16, BB * HH), blk>>>(attn, pv, po);

    // Output projection
    proj_mma<<<dim3(DD / 128, BS / 128), blk>>>(
        HH * HD, po, HH * HD, wo, HH * HD, out, DD);
}

// round 16
// speedup vs baseline: 1.0679x; 1.0165x over previous
#include <cuda_runtime.h>
#include <cuda_bf16.h>
#include <math.h>
#include <stdint.h>

#define BB   2
#define SS   2048
#define DD   2048
#define HH   16
#define KVH  8
#define GG   2
#define HD   128
#define SCALE 0.08838834764831845f

typedef __nv_bfloat16 bf16;
typedef __nv_bfloat162 bf162;

// ---------------- persistent scratch ----------------
__device__ float g_q[(size_t)BB * SS * HH  * HD];   // (B,S,H,HD)
__device__ float g_k[(size_t)BB * SS * KVH * HD];   // (B,S,KV,HD)
__device__ float g_v[(size_t)BB * SS * KVH * HD];   // (B,S,KV,HD)
__device__ float g_o[(size_t)BB * SS * HH  * HD];   // (B,S,H,HD)

// ---------------- PTX helpers ----------------
__device__ __forceinline__ uint32_t smaddr(const void* p) {
    return (uint32_t)__cvta_generic_to_shared(p);
}
__device__ __forceinline__ void ldsm_x4(uint32_t* r, uint32_t addr) {
    asm volatile("ldmatrix.sync.aligned.m8n8.x4.shared.b16 {%0,%1,%2,%3}, [%4];"
        : "=r"(r[0]), "=r"(r[1]), "=r"(r[2]), "=r"(r[3]) : "r"(addr));
}
__device__ __forceinline__ void ldsm_x2(uint32_t* r, uint32_t addr) {
    asm volatile("ldmatrix.sync.aligned.m8n8.x2.shared.b16 {%0,%1}, [%2];"
        : "=r"(r[0]), "=r"(r[1]) : "r"(addr));
}
__device__ __forceinline__ void ldsm_x2t(uint32_t* r, uint32_t addr) {
    asm volatile("ldmatrix.sync.aligned.m8n8.x2.trans.shared.b16 {%0,%1}, [%2];"
        : "=r"(r[0]), "=r"(r[1]) : "r"(addr));
}
__device__ __forceinline__ void mma_bf16(float* c, const uint32_t* a, const uint32_t* b) {
    asm volatile(
        "mma.sync.aligned.m16n8k16.row.col.f32.bf16.bf16.f32 "
        "{%0,%1,%2,%3}, {%4,%5,%6,%7}, {%8,%9}, {%0,%1,%2,%3};"
        : "+f"(c[0]), "+f"(c[1]), "+f"(c[2]), "+f"(c[3])
        : "r"(a[0]), "r"(a[1]), "r"(a[2]), "r"(a[3]), "r"(b[0]), "r"(b[1]));
}
__device__ __forceinline__ void split_store(float4 v, bf16* hi, bf16* lo) {
    bf162 H0 = __floats2bfloat162_rn(v.x, v.y);
    bf162 H1 = __floats2bfloat162_rn(v.z, v.w);
    bf162 L0 = __floats2bfloat162_rn(v.x - __low2float(H0), v.y - __high2float(H0));
    bf162 L1 = __floats2bfloat162_rn(v.z - __low2float(H1), v.w - __high2float(H1));
    *(bf162*)hi       = H0;
    *(bf162*)(hi + 2) = H1;
    *(bf162*)lo       = L0;
    *(bf162*)(lo + 2) = L1;
}

// ---------------------------------------------------------------------------
// bf16x3 split GEMM core (unchanged best core) — used by qkv / wo / av.
// ---------------------------------------------------------------------------
#define AROW 40
#define BROWN 136

template<bool BTRANS>
__device__ __forceinline__ void gemm_core(
    const float* __restrict__ A, int lda,
    const float* __restrict__ B, int ldb,
    float* __restrict__ C, int ldc, int K, float alpha)
{
    __shared__ __align__(16) __nv_bfloat16 sAh[128 * AROW];
    __shared__ __align__(16) __nv_bfloat16 sAl[128 * AROW];
    __shared__ __align__(16) __nv_bfloat16 sBh[5120];
    __shared__ __align__(16) __nv_bfloat16 sBl[5120];

    const int tid  = threadIdx.x;
    const int lane = tid & 31;
    const int wid  = tid >> 5;
    const int wm   = (wid >> 2) << 6;   // 0 or 64
    const int wn   = (wid & 3) << 5;    // 0,32,64,96

    float acc[4][4][4];
#pragma unroll
    for (int i = 0; i < 4; ++i)
#pragma unroll
        for (int j = 0; j < 4; ++j)
#pragma unroll
            for (int l = 0; l < 4; ++l) acc[i][j][l] = 0.f;

    for (int k0 = 0; k0 < K; k0 += 32) {
        {
            int r = tid >> 3;
            const int c = (tid & 7) << 2;
#pragma unroll
            for (int p = 0; p < 4; ++p, r += 32) {
                float4 v = *(const float4*)(A + (size_t)r * lda + k0 + c);
                split_store(v, &sAh[r * AROW + c], &sAl[r * AROW + c]);
            }
        }
        if (BTRANS) {
            int r = tid >> 3;
            const int c = (tid & 7) << 2;
#pragma unroll
            for (int p = 0; p < 4; ++p, r += 32) {
                float4 v = *(const float4*)(B + (size_t)r * ldb + k0 + c);
                split_store(v, &sBh[r * AROW + c], &sBl[r * AROW + c]);
            }
        } else {
            int r = tid >> 5;
            const int c = (tid & 31) << 2;
#pragma unroll
            for (int p = 0; p < 4; ++p, r += 8) {
                float4 v = *(const float4*)(B + (size_t)(k0 + r) * ldb + c);
                split_store(v, &sBh[r * BROWN + c], &sBl[r * BROWN + c]);
            }
        }
        __syncthreads();

#pragma unroll
        for (int ks = 0; ks < 2; ++ks) {
            uint32_t af[4][4];
            uint32_t bh[4][2];
            uint32_t bl[4][2];

            const int arow_off = (lane & 15);
            const int akb = ks * 32 + ((lane >> 4) << 4);

#pragma unroll
            for (int mt = 0; mt < 4; ++mt)
                ldsm_x4(af[mt], smaddr(&sAh[(wm + mt * 16 + arow_off) * AROW]) + akb);

#pragma unroll
            for (int nt = 0; nt < 4; ++nt) {
                if (BTRANS) {
                    uint32_t ad = smaddr(&sBh[(wn + nt * 8 + (lane & 7)) * AROW])
                                + ks * 32 + (((lane >> 3) & 1) << 4);
                    ldsm_x2(bh[nt], ad);
                } else {
                    uint32_t ad = smaddr(&sBh[(ks * 16 + (lane & 15)) * BROWN + wn + nt * 8]);
                    ldsm_x2t(bh[nt], ad);
                }
            }
#pragma unroll
            for (int mt = 0; mt < 4; ++mt)
#pragma unroll
                for (int nt = 0; nt < 4; ++nt)
                    mma_bf16(acc[mt][nt], af[mt], bh[nt]);

#pragma unroll
            for (int nt = 0; nt < 4; ++nt) {
                if (BTRANS) {
                    uint32_t ad = smaddr(&sBl[(wn + nt * 8 + (lane & 7)) * AROW])
                                + ks * 32 + (((lane >> 3) & 1) << 4);
                    ldsm_x2(bl[nt], ad);
                } else {
                    uint32_t ad = smaddr(&sBl[(ks * 16 + (lane & 15)) * BROWN + wn + nt * 8]);
                    ldsm_x2t(bl[nt], ad);
                }
            }
#pragma unroll
            for (int mt = 0; mt < 4; ++mt)
#pragma unroll
                for (int nt = 0; nt < 4; ++nt)
                    mma_bf16(acc[mt][nt], af[mt], bl[nt]);

#pragma unroll
            for (int mt = 0; mt < 4; ++mt)
                ldsm_x4(af[mt], smaddr(&sAl[(wm + mt * 16 + arow_off) * AROW]) + akb);
#pragma unroll
            for (int mt = 0; mt < 4; ++mt)
#pragma unroll
                for (int nt = 0; nt < 4; ++nt)
                    mma_bf16(acc[mt][nt], af[mt], bh[nt]);
        }
        __syncthreads();
    }

#pragma unroll
    for (int mt = 0; mt < 4; ++mt) {
#pragma unroll
        for (int nt = 0; nt < 4; ++nt) {
            int r = wm + mt * 16 + (lane >> 2);
            int c = wn + nt * 8 + ((lane & 3) << 1);
            float2 v0 = make_float2(alpha * acc[mt][nt][0], alpha * acc[mt][nt][1]);
            float2 v1 = make_float2(alpha * acc[mt][nt][2], alpha * acc[mt][nt][3]);
            *(float2*)&C[(size_t)r * ldc + c]       = v0;
            *(float2*)&C[(size_t)(r + 8) * ldc + c] = v1;
        }
    }
}

// ---------------------------------------------------------------------------
// Fused QKV projection
// ---------------------------------------------------------------------------
__global__ __launch_bounds__(256, 2) void qkv_mma(
    const float* __restrict__ x,
    const float* __restrict__ wq, const float* __restrict__ wk,
    const float* __restrict__ wv,
    float* __restrict__ q, float* __restrict__ k, float* __restrict__ v)
{
    const int n0 = blockIdx.x * 128;
    const float* A = x + (size_t)blockIdx.y * 128 * DD;

    if (n0 < HH * HD) {
        const float* B = wq + (size_t)n0 * DD;
        float* C = q + (size_t)blockIdx.y * 128 * (HH * HD) + n0;
        gemm_core<true>(A, DD, B, DD, C, HH * HD, DD, 1.0f);
    } else if (n0 < HH * HD + KVH * HD) {
        const int m = n0 - HH * HD;
        const float* B = wk + (size_t)m * DD;
        float* C = k + (size_t)blockIdx.y * 128 * (KVH * HD) + m;
        gemm_core<true>(A, DD, B, DD, C, KVH * HD, DD, 1.0f);
    } else {
        const int m = n0 - HH * HD - KVH * HD;
        const float* B = wv + (size_t)m * DD;
        float* C = v + (size_t)blockIdx.y * 128 * (KVH * HD) + m;
        gemm_core<true>(A, DD, B, DD, C, KVH * HD, DD, 1.0f);
    }
}

__global__ __launch_bounds__(256, 2) void proj_mma(
    int K, const float* __restrict__ A, int lda,
    const float* __restrict__ B, int ldb, float* __restrict__ C, int ldc)
{
    const float* Ab = A + (size_t)blockIdx.y * 128 * lda;
    const float* Bb = B + (size_t)blockIdx.x * 128 * ldb;
    float* Cb = C + (size_t)blockIdx.y * 128 * ldc + (size_t)blockIdx.x * 128;
    gemm_core<true>(Ab, lda, Bb, ldb, Cb, ldc, K, 1.0f);
}

// ---------------------------------------------------------------------------
// GQA-paired score kernel (R13, 2 CTAs/SM): K tile staged once in 68KB
// dynamic smem; Q chunks staged per head. Zero tiles for upper triangle.
// ---------------------------------------------------------------------------
#define KROW 136
#define SCORE_DSM (2 * 128 * KROW * 2)   // 69632 B

__global__ __launch_bounds__(256, 2) void score_pair(
    const float* __restrict__ q, const float* __restrict__ k,
    float* __restrict__ attn)
{
    extern __shared__ __align__(16) bf16 dyn[];
    bf16* sBh = dyn;
    bf16* sBl = dyn + 128 * KROW;
    __shared__ __align__(16) bf16 sAh[128 * AROW];
    __shared__ __align__(16) bf16 sAl[128 * AROW];

    const int x = blockIdx.x, y = blockIdx.y;
    const int bkv = blockIdx.z;
    const int b = bkv / KVH, kv = bkv % KVH;
    const int h0 = kv * GG;

    const int tid  = threadIdx.x;
    const int lane = tid & 31;
    const int wid  = tid >> 5;
    const int wm   = (wid >> 2) << 6;
    const int wn   = (wid & 3) << 5;

    if (x > y) {
        const float4 z = make_float4(0.f, 0.f, 0.f, 0.f);
#pragma unroll
        for (int g = 0; g < GG; ++g) {
            float* C = attn + ((size_t)(b * HH + h0 + g)) * SS * SS
                     + (size_t)y * 128 * SS + (size_t)x * 128;
            for (int t = tid; t < 128 * 32; t += 256) {
                int r = t >> 5, c = (t & 31) << 2;
                *(float4*)&C[(size_t)r * SS + c] = z;
            }
        }
        return;
    }

    // stage FULL K tile (128 rows x 128 K) once, hi/lo split
    const float* B = k + ((size_t)b * SS * KVH + kv) * HD
                       + (size_t)x * 128 * (KVH * HD);
    const int ldb = KVH * HD;
    for (int t = tid; t < 128 * 32; t += 256) {
        int r = t >> 5, c = (t & 31) << 2;
        float4 v = *(const float4*)(B + (size_t)r * ldb + c);
        split_store(v, &sBh[r * KROW + c], &sBl[r * KROW + c]);
    }
    __syncthreads();

#pragma unroll
    for (int g = 0; g < GG; ++g) {
        const float* A = q + ((size_t)b * SS * HH + h0 + g) * HD
                           + (size_t)y * 128 * (HH * HD);
        float* C = attn + ((size_t)(b * HH + h0 + g)) * SS * SS
                 + (size_t)y * 128 * SS + (size_t)x * 128;
        const int lda = HH * HD;

        float acc[4][4][4];
#pragma unroll
        for (int i = 0; i < 4; ++i)
#pragma unroll
            for (int j = 0; j < 4; ++j)
#pragma unroll
                for (int l = 0; l < 4; ++l) acc[i][j][l] = 0.f;

#pragma unroll
        for (int ch = 0; ch < 4; ++ch) {
            {
                int r = tid >> 3;
                const int c = (tid & 7) << 2;
#pragma unroll
                for (int p = 0; p < 4; ++p, r += 32) {
                    float4 v = *(const float4*)(A + (size_t)r * lda + ch * 32 + c);
                    split_store(v, &sAh[r * AROW + c], &sAl[r * AROW + c]);
                }
            }
            __syncthreads();

#pragma unroll
            for (int ks = 0; ks < 2; ++ks) {
                uint32_t af[4][4], bh[4][2], bl[4][2];
                const int arow_off = (lane & 15);
                const int akb = ks * 32 + ((lane >> 4) << 4);
                const int bkb = ch * 64 + ks * 32 + (((lane >> 3) & 1) << 4);

#pragma unroll
                for (int mt = 0; mt < 4; ++mt)
                    ldsm_x4(af[mt], smaddr(&sAh[(wm + mt * 16 + arow_off) * AROW]) + akb);
#pragma unroll
                for (int nt = 0; nt < 4; ++nt)
                    ldsm_x2(bh[nt], smaddr(&sBh[(wn + nt * 8 + (lane & 7)) * KROW]) + bkb);
#pragma unroll
                for (int mt = 0; mt < 4; ++mt)
#pragma unroll
                    for (int nt = 0; nt < 4; ++nt) mma_bf16(acc[mt][nt], af[mt], bh[nt]);

#pragma unroll
                for (int nt = 0; nt < 4; ++nt)
                    ldsm_x2(bl[nt], smaddr(&sBl[(wn + nt * 8 + (lane & 7)) * KROW]) + bkb);
#pragma unroll
                for (int mt = 0; mt < 4; ++mt)
#pragma unroll
                    for (int nt = 0; nt < 4; ++nt) mma_bf16(acc[mt][nt], af[mt], bl[nt]);

#pragma unroll
                for (int mt = 0; mt < 4; ++mt)
                    ldsm_x4(af[mt], smaddr(&sAl[(wm + mt * 16 + arow_off) * AROW]) + akb);
#pragma unroll
                for (int mt = 0; mt < 4; ++mt)
#pragma unroll
                    for (int nt = 0; nt < 4; ++nt) mma_bf16(acc[mt][nt], af[mt], bh[nt]);
            }
            __syncthreads();
        }

#pragma unroll
        for (int mt = 0; mt < 4; ++mt) {
#pragma unroll
            for (int nt = 0; nt < 4; ++nt) {
                int r = wm + mt * 16 + (lane >> 2);
                int c = wn + nt * 8 + ((lane & 3) << 1);
                float2 v0 = make_float2(SCALE * acc[mt][nt][0], SCALE * acc[mt][nt][1]);
                float2 v1 = make_float2(SCALE * acc[mt][nt][2], SCALE * acc[mt][nt][3]);
                *(float2*)&C[(size_t)r * SS + c]       = v0;
                *(float2*)&C[(size_t)(r + 8) * SS + c] = v1;
            }
        }
    }
}

// AV (NN core + heavy-first scheduling)
__global__ __launch_bounds__(256, 2) void av_mma(
    const float* __restrict__ attn, const float* __restrict__ v,
    float* __restrict__ o)
{
    const int ry = 15 - (int)blockIdx.y;       // heavy first (LPT)
    const int bh = blockIdx.z;
    const int h = bh % HH, b = bh / HH, kv = h / GG;
    const float* A = attn + (size_t)bh * SS * SS + (size_t)ry * 128 * SS;
    const float* B = v + ((size_t)b * SS * KVH + kv) * HD;
    float* C = o + ((size_t)b * SS * HH + h) * HD
                 + (size_t)ry * 128 * (HH * HD);
    const int K = (ry + 1) * 128;
    gemm_core<false>(A, SS, B, KVH * HD, C, HH * HD, K, 1.0f);
}

// ---------------------------------------------------------------------------
// Fused RMSNorm + RoPE, in place (fp32) — R13 version, two launches.
// ---------------------------------------------------------------------------
__global__ __launch_bounds__(128) void normrope_kernel(
    float* __restrict__ data, const float* __restrict__ w,
    const float* __restrict__ cosb, const float* __restrict__ sinb,
    int nheads)
{
    const int idx = blockIdx.x;
    const int h = idx % nheads;
    const int s = (idx / nheads) % SS;
    const int b = idx / (nheads * SS);
    const int t = threadIdx.x;

    float* ptr = data + (((size_t)b * SS + s) * nheads + h) * HD;
    float v = ptr[t];

    float ss = v * v;
#pragma unroll
    for (int o = 16; o; o >>= 1) ss += __shfl_xor_sync(0xffffffffu, ss, o);

    __shared__ float ws[4];
    __shared__ float sh[128];
    const int lane = t & 31, wid = t >> 5;
    if (lane == 0) ws[wid] = ss;
    __syncthreads();
    float var = (ws[0] + ws[1] + ws[2] + ws[3]) * (1.0f / HD);
    float xn = v * rsqrtf(var + 1e-6f) * w[t];
    sh[t] = xn;
    __syncthreads();
    float rot = (t < 64) ? -sh[t + 64] : sh[t - 64];

    const float* cp = cosb + ((size_t)b * SS + s) * HD;
    const float* sp = sinb + ((size_t)b * SS + s) * HD;
    ptr[t] = xn * cp[t] + rot * sp[t];
}

// ---------------------------------------------------------------------------
// Row softmax (causal), REGISTER-RESIDENT: row (<=2048 elems / 256 threads)
// fits in 2 float4 per thread — no smem buffer. Span-only writes, __expf.
// ---------------------------------------------------------------------------
__global__ __launch_bounds__(256) void softmax_kernel(float* __restrict__ attn)
{
    __shared__ float redm[8];
    __shared__ float reds[8];
    const int row = blockIdx.x;
    const int qi = row & (SS - 1);
    const int valid = qi + 1;
    const int span = ((qi >> 7) + 1) << 7;     // next multiple of 128
    float* base = attn + (size_t)row * SS;
    const int tid = threadIdx.x;
    const int lane = tid & 31, wrp = tid >> 5;

    float4 r0, r1;
    const int t0 = tid * 4;
    const int t1 = t0 + 1024;
    const bool a0 = (t0 < span);
    const bool a1 = (t1 < span);

    float m = -1e30f;
    if (a0) {
        float4 v = *(const float4*)(base + t0);
        v.x = (t0 + 0 < valid) ? v.x : -1e30f;
        v.y = (t0 + 1 < valid) ? v.y : -1e30f;
        v.z = (t0 + 2 < valid) ? v.z : -1e30f;
        v.w = (t0 + 3 < valid) ? v.w : -1e30f;
        r0 = v;
        m = fmaxf(m, fmaxf(fmaxf(v.x, v.y), fmaxf(v.z, v.w)));
    }
    if (a1) {
        float4 v = *(const float4*)(base + t1);
        v.x = (t1 + 0 < valid) ? v.x : -1e30f;
        v.y = (t1 + 1 < valid) ? v.y : -1e30f;
        v.z = (t1 + 2 < valid) ? v.z : -1e30f;
        v.w = (t1 + 3 < valid) ? v.w : -1e30f;
        r1 = v;
        m = fmaxf(m, fmaxf(fmaxf(v.x, v.y), fmaxf(v.z, v.w)));
    }
#pragma unroll
    for (int o = 16; o; o >>= 1) m = fmaxf(m, __shfl_xor_sync(0xffffffffu, m, o));
    if (lane == 0) redm[wrp] = m;
    __syncthreads();
    float mx = redm[0];
#pragma unroll
    for (int i = 1; i < 8; ++i) mx = fmaxf(mx, redm[i]);

    float sum = 0.f;
    if (a0) {
        r0.x = __expf(r0.x - mx); r0.y = __expf(r0.y - mx);
        r0.z = __expf(r0.z - mx); r0.w = __expf(r0.w - mx);
        sum += r0.x + r0.y + r0.z + r0.w;
    }
    if (a1) {
        r1.x = __expf(r1.x - mx); r1.y = __expf(r1.y - mx);
        r1.z = __expf(r1.z - mx); r1.w = __expf(r1.w - mx);
        sum += r1.x + r1.y + r1.z + r1.w;
    }
#pragma unroll
    for (int o = 16; o; o >>= 1) sum += __shfl_xor_sync(0xffffffffu, sum, o);
    if (lane == 0) reds[wrp] = sum;
    __syncthreads();
    float tot = reds[0] + reds[1] + reds[2] + reds[3]
              + reds[4] + reds[5] + reds[6] + reds[7];
    const float inv = 1.0f / tot;

    if (a0) {
        r0.x *= inv; r0.y *= inv; r0.z *= inv; r0.w *= inv;
        *(float4*)(base + t0) = r0;
    }
    if (a1) {
        r1.x *= inv; r1.y *= inv; r1.z *= inv; r1.w *= inv;
        *(float4*)(base + t1) = r1;
    }
}

// ---------------- launch ----------------
extern "C" void kernel_launch(void* const* d_in, const int* in_sizes, int n_in,
                              void* d_out, int out_size)
{
    const float* x    = (const float*)d_in[0];
    const float* cosb = (const float*)d_in[1];
    const float* sinb = (const float*)d_in[2];
    // d_in[3] = attention_mask (pure causal; applied analytically)
    const float* wq   = (const float*)d_in[4];
    const float* wk   = (const float*)d_in[5];
    const float* wv   = (const float*)d_in[6];
    const float* wo   = (const float*)d_in[7];
    const float* qw   = (const float*)d_in[8];
    const float* kw   = (const float*)d_in[9];

    float* out  = (float*)d_out;                    // (B,S,H*HD)
    float* attn = out + (size_t)BB * SS * HH * HD;  // (B,H,S,S)

    float *pq, *pk, *pv, *po;
    cudaGetSymbolAddress((void**)&pq, g_q);
    cudaGetSymbolAddress((void**)&pk, g_k);
    cudaGetSymbolAddress((void**)&pv, g_v);
    cudaGetSymbolAddress((void**)&po, g_o);

    cudaFuncSetAttribute(score_pair,
                         cudaFuncAttributeMaxDynamicSharedMemorySize, SCORE_DSM);

    const int BS = BB * SS;   // 4096
    dim3 blk(256);

    // Fused QKV projection
    qkv_mma<<<dim3(32, BS / 128), blk>>>(x, wq, wk, wv, pq, pk, pv);

    // RMSNorm + RoPE (in place, fp32)
    normrope_kernel<<<BB * SS * HH, 128>>>(pq, qw, cosb, sinb, HH);
    normrope_kernel<<<BB * SS * KVH, 128>>>(pk, kw, cosb, sinb, KVH);

    // Scores: GQA-paired, K tile staged once per pair; zero tiles included
    score_pair<<<dim3(SS / 128, SS / 128, BB * KVH), blk, SCORE_DSM>>>(pq, pk, attn);

    // Softmax (register-resident, span-only), AV (heavy-first)
    softmax_kernel<<<BB * HH * SS, 256>>>(attn);
    av_mma<<<dim3(1, 16, BB * HH), blk>>>(attn, pv, po);

    // Output projection
    proj_mma<<<dim3(DD / 128, BS / 128), blk>>>(
        HH * HD, po, HH * HD, wo, HH * HD, out, DD);
}

// round 17
// speedup vs baseline: 1.1012x; 1.0312x over previous
#include <cuda_runtime.h>
#include <cuda_bf16.h>
#include <math.h>
#include <stdint.h>

#define BB   2
#define SS   2048
#define DD   2048
#define HH   16
#define KVH  8
#define GG   2
#define HD   128
#define SCALE 0.08838834764831845f

typedef __nv_bfloat16 bf16;
typedef __nv_bfloat162 bf162;

// ---------------- persistent scratch ----------------
__device__ float g_q[(size_t)BB * SS * HH  * HD];   // (B,S,H,HD)
__device__ float g_k[(size_t)BB * SS * KVH * HD];   // (B,S,KV,HD)
__device__ float g_v[(size_t)BB * SS * KVH * HD];   // (B,S,KV,HD)
__device__ float g_o[(size_t)BB * SS * HH  * HD];   // (B,S,H,HD)

// ---------------- PTX helpers ----------------
__device__ __forceinline__ uint32_t smaddr(const void* p) {
    return (uint32_t)__cvta_generic_to_shared(p);
}
__device__ __forceinline__ void ldsm_x4(uint32_t* r, uint32_t addr) {
    asm volatile("ldmatrix.sync.aligned.m8n8.x4.shared.b16 {%0,%1,%2,%3}, [%4];"
        : "=r"(r[0]), "=r"(r[1]), "=r"(r[2]), "=r"(r[3]) : "r"(addr));
}
__device__ __forceinline__ void ldsm_x2(uint32_t* r, uint32_t addr) {
    asm volatile("ldmatrix.sync.aligned.m8n8.x2.shared.b16 {%0,%1}, [%2];"
        : "=r"(r[0]), "=r"(r[1]) : "r"(addr));
}
__device__ __forceinline__ void ldsm_x2t(uint32_t* r, uint32_t addr) {
    asm volatile("ldmatrix.sync.aligned.m8n8.x2.trans.shared.b16 {%0,%1}, [%2];"
        : "=r"(r[0]), "=r"(r[1]) : "r"(addr));
}
__device__ __forceinline__ void mma_bf16(float* c, const uint32_t* a, const uint32_t* b) {
    asm volatile(
        "mma.sync.aligned.m16n8k16.row.col.f32.bf16.bf16.f32 "
        "{%0,%1,%2,%3}, {%4,%5,%6,%7}, {%8,%9}, {%0,%1,%2,%3};"
        : "+f"(c[0]), "+f"(c[1]), "+f"(c[2]), "+f"(c[3])
        : "r"(a[0]), "r"(a[1]), "r"(a[2]), "r"(a[3]), "r"(b[0]), "r"(b[1]));
}
__device__ __forceinline__ void split_store(float4 v, bf16* hi, bf16* lo) {
    bf162 H0 = __floats2bfloat162_rn(v.x, v.y);
    bf162 H1 = __floats2bfloat162_rn(v.z, v.w);
    bf162 L0 = __floats2bfloat162_rn(v.x - __low2float(H0), v.y - __high2float(H0));
    bf162 L1 = __floats2bfloat162_rn(v.z - __low2float(H1), v.w - __high2float(H1));
    *(bf162*)hi       = H0;
    *(bf162*)(hi + 2) = H1;
    *(bf162*)lo       = L0;
    *(bf162*)(lo + 2) = L1;
}

// ---------------------------------------------------------------------------
// bf16x3 split GEMM core (unchanged best core) — used by qkv / wo / av.
// ---------------------------------------------------------------------------
#define AROW 40
#define BROWN 136

template<bool BTRANS>
__device__ __forceinline__ void gemm_core(
    const float* __restrict__ A, int lda,
    const float* __restrict__ B, int ldb,
    float* __restrict__ C, int ldc, int K, float alpha)
{
    __shared__ __align__(16) __nv_bfloat16 sAh[128 * AROW];
    __shared__ __align__(16) __nv_bfloat16 sAl[128 * AROW];
    __shared__ __align__(16) __nv_bfloat16 sBh[5120];
    __shared__ __align__(16) __nv_bfloat16 sBl[5120];

    const int tid  = threadIdx.x;
    const int lane = tid & 31;
    const int wid  = tid >> 5;
    const int wm   = (wid >> 2) << 6;   // 0 or 64
    const int wn   = (wid & 3) << 5;    // 0,32,64,96

    float acc[4][4][4];
#pragma unroll
    for (int i = 0; i < 4; ++i)
#pragma unroll
        for (int j = 0; j < 4; ++j)
#pragma unroll
            for (int l = 0; l < 4; ++l) acc[i][j][l] = 0.f;

    for (int k0 = 0; k0 < K; k0 += 32) {
        {
            int r = tid >> 3;
            const int c = (tid & 7) << 2;
#pragma unroll
            for (int p = 0; p < 4; ++p, r += 32) {
                float4 v = *(const float4*)(A + (size_t)r * lda + k0 + c);
                split_store(v, &sAh[r * AROW + c], &sAl[r * AROW + c]);
            }
        }
        if (BTRANS) {
            int r = tid >> 3;
            const int c = (tid & 7) << 2;
#pragma unroll
            for (int p = 0; p < 4; ++p, r += 32) {
                float4 v = *(const float4*)(B + (size_t)r * ldb + k0 + c);
                split_store(v, &sBh[r * AROW + c], &sBl[r * AROW + c]);
            }
        } else {
            int r = tid >> 5;
            const int c = (tid & 31) << 2;
#pragma unroll
            for (int p = 0; p < 4; ++p, r += 8) {
                float4 v = *(const float4*)(B + (size_t)(k0 + r) * ldb + c);
                split_store(v, &sBh[r * BROWN + c], &sBl[r * BROWN + c]);
            }
        }
        __syncthreads();

#pragma unroll
        for (int ks = 0; ks < 2; ++ks) {
            uint32_t af[4][4];
            uint32_t bh[4][2];
            uint32_t bl[4][2];

            const int arow_off = (lane & 15);
            const int akb = ks * 32 + ((lane >> 4) << 4);

#pragma unroll
            for (int mt = 0; mt < 4; ++mt)
                ldsm_x4(af[mt], smaddr(&sAh[(wm + mt * 16 + arow_off) * AROW]) + akb);

#pragma unroll
            for (int nt = 0; nt < 4; ++nt) {
                if (BTRANS) {
                    uint32_t ad = smaddr(&sBh[(wn + nt * 8 + (lane & 7)) * AROW])
                                + ks * 32 + (((lane >> 3) & 1) << 4);
                    ldsm_x2(bh[nt], ad);
                } else {
                    uint32_t ad = smaddr(&sBh[(ks * 16 + (lane & 15)) * BROWN + wn + nt * 8]);
                    ldsm_x2t(bh[nt], ad);
                }
            }
#pragma unroll
            for (int mt = 0; mt < 4; ++mt)
#pragma unroll
                for (int nt = 0; nt < 4; ++nt)
                    mma_bf16(acc[mt][nt], af[mt], bh[nt]);

#pragma unroll
            for (int nt = 0; nt < 4; ++nt) {
                if (BTRANS) {
                    uint32_t ad = smaddr(&sBl[(wn + nt * 8 + (lane & 7)) * AROW])
                                + ks * 32 + (((lane >> 3) & 1) << 4);
                    ldsm_x2(bl[nt], ad);
                } else {
                    uint32_t ad = smaddr(&sBl[(ks * 16 + (lane & 15)) * BROWN + wn + nt * 8]);
                    ldsm_x2t(bl[nt], ad);
                }
            }
#pragma unroll
            for (int mt = 0; mt < 4; ++mt)
#pragma unroll
                for (int nt = 0; nt < 4; ++nt)
                    mma_bf16(acc[mt][nt], af[mt], bl[nt]);

#pragma unroll
            for (int mt = 0; mt < 4; ++mt)
                ldsm_x4(af[mt], smaddr(&sAl[(wm + mt * 16 + arow_off) * AROW]) + akb);
#pragma unroll
            for (int mt = 0; mt < 4; ++mt)
#pragma unroll
                for (int nt = 0; nt < 4; ++nt)
                    mma_bf16(acc[mt][nt], af[mt], bh[nt]);
        }
        __syncthreads();
    }

#pragma unroll
    for (int mt = 0; mt < 4; ++mt) {
#pragma unroll
        for (int nt = 0; nt < 4; ++nt) {
            int r = wm + mt * 16 + (lane >> 2);
            int c = wn + nt * 8 + ((lane & 3) << 1);
            float2 v0 = make_float2(alpha * acc[mt][nt][0], alpha * acc[mt][nt][1]);
            float2 v1 = make_float2(alpha * acc[mt][nt][2], alpha * acc[mt][nt][3]);
            *(float2*)&C[(size_t)r * ldc + c]       = v0;
            *(float2*)&C[(size_t)(r + 8) * ldc + c] = v1;
        }
    }
}

// ---------------------------------------------------------------------------
// Fused QKV projection + causal zero-fill CTAs (x >= 32).
// Zero CTAs pre-fill the attn upper triangle (no dependencies), overlapping
// with the compute-bound QKV GEMM.
// ---------------------------------------------------------------------------
__global__ __launch_bounds__(256, 2) void qkv_mma(
    const float* __restrict__ x,
    const float* __restrict__ wq, const float* __restrict__ wk,
    const float* __restrict__ wv,
    float* __restrict__ q, float* __restrict__ k, float* __restrict__ v,
    float* __restrict__ attn)
{
    const int bx = blockIdx.x;
    if (bx >= 32) {
        // zero-fill lane: bh = blockIdx.y, tiles where xt > yt, strided by 4
        const int xe = bx - 32;                 // 0..3
        const int bh = blockIdx.y;              // 0..31
        float* base = attn + (size_t)bh * SS * SS;
        const float4 z = make_float4(0.f, 0.f, 0.f, 0.f);
        int cnt = 0;
        for (int yt = 0; yt < 16; ++yt) {
            for (int xt = yt + 1; xt < 16; ++xt, ++cnt) {
                if ((cnt & 3) != xe) continue;
                float* C = base + (size_t)yt * 128 * SS + (size_t)xt * 128;
                for (int t = threadIdx.x; t < 128 * 32; t += 256) {
                    int r = t >> 5, c = (t & 31) << 2;
                    *(float4*)&C[(size_t)r * SS + c] = z;
                }
            }
        }
        return;
    }

    const int n0 = bx * 128;
    const float* A = x + (size_t)blockIdx.y * 128 * DD;

    if (n0 < HH * HD) {
        const float* B = wq + (size_t)n0 * DD;
        float* C = q + (size_t)blockIdx.y * 128 * (HH * HD) + n0;
        gemm_core<true>(A, DD, B, DD, C, HH * HD, DD, 1.0f);
    } else if (n0 < HH * HD + KVH * HD) {
        const int m = n0 - HH * HD;
        const float* B = wk + (size_t)m * DD;
        float* C = k + (size_t)blockIdx.y * 128 * (KVH * HD) + m;
        gemm_core<true>(A, DD, B, DD, C, KVH * HD, DD, 1.0f);
    } else {
        const int m = n0 - HH * HD - KVH * HD;
        const float* B = wv + (size_t)m * DD;
        float* C = v + (size_t)blockIdx.y * 128 * (KVH * HD) + m;
        gemm_core<true>(A, DD, B, DD, C, KVH * HD, DD, 1.0f);
    }
}

__global__ __launch_bounds__(256, 2) void proj_mma(
    int K, const float* __restrict__ A, int lda,
    const float* __restrict__ B, int ldb, float* __restrict__ C, int ldc)
{
    const float* Ab = A + (size_t)blockIdx.y * 128 * lda;
    const float* Bb = B + (size_t)blockIdx.x * 128 * ldb;
    float* Cb = C + (size_t)blockIdx.y * 128 * ldc + (size_t)blockIdx.x * 128;
    gemm_core<true>(Ab, lda, Bb, ldb, Cb, ldc, K, 1.0f);
}

// ---------------------------------------------------------------------------
// GQA-paired score kernel (R13, 2 CTAs/SM): K tile staged once in 68KB
// dynamic smem; Q chunks staged per head. Upper-triangle CTAs return
// immediately (zero-fill moved to qkv launch).
// ---------------------------------------------------------------------------
#define KROW 136
#define SCORE_DSM (2 * 128 * KROW * 2)   // 69632 B

__global__ __launch_bounds__(256, 2) void score_pair(
    const float* __restrict__ q, const float* __restrict__ k,
    float* __restrict__ attn)
{
    const int x = blockIdx.x, y = blockIdx.y;
    if (x > y) return;                  // zero region pre-filled by qkv launch

    extern __shared__ __align__(16) bf16 dyn[];
    bf16* sBh = dyn;
    bf16* sBl = dyn + 128 * KROW;
    __shared__ __align__(16) bf16 sAh[128 * AROW];
    __shared__ __align__(16) bf16 sAl[128 * AROW];

    const int bkv = blockIdx.z;
    const int b = bkv / KVH, kv = bkv % KVH;
    const int h0 = kv * GG;

    const int tid  = threadIdx.x;
    const int lane = tid & 31;
    const int wid  = tid >> 5;
    const int wm   = (wid >> 2) << 6;
    const int wn   = (wid & 3) << 5;

    // stage FULL K tile (128 rows x 128 K) once, hi/lo split
    const float* B = k + ((size_t)b * SS * KVH + kv) * HD
                       + (size_t)x * 128 * (KVH * HD);
    const int ldb = KVH * HD;
    for (int t = tid; t < 128 * 32; t += 256) {
        int r = t >> 5, c = (t & 31) << 2;
        float4 v = *(const float4*)(B + (size_t)r * ldb + c);
        split_store(v, &sBh[r * KROW + c], &sBl[r * KROW + c]);
    }
    __syncthreads();

#pragma unroll
    for (int g = 0; g < GG; ++g) {
        const float* A = q + ((size_t)b * SS * HH + h0 + g) * HD
                           + (size_t)y * 128 * (HH * HD);
        float* C = attn + ((size_t)(b * HH + h0 + g)) * SS * SS
                 + (size_t)y * 128 * SS + (size_t)x * 128;
        const int lda = HH * HD;

        float acc[4][4][4];
#pragma unroll
        for (int i = 0; i < 4; ++i)
#pragma unroll
            for (int j = 0; j < 4; ++j)
#pragma unroll
                for (int l = 0; l < 4; ++l) acc[i][j][l] = 0.f;

#pragma unroll
        for (int ch = 0; ch < 4; ++ch) {
            {
                int r = tid >> 3;
                const int c = (tid & 7) << 2;
#pragma unroll
                for (int p = 0; p < 4; ++p, r += 32) {
                    float4 v = *(const float4*)(A + (size_t)r * lda + ch * 32 + c);
                    split_store(v, &sAh[r * AROW + c], &sAl[r * AROW + c]);
                }
            }
            __syncthreads();

#pragma unroll
            for (int ks = 0; ks < 2; ++ks) {
                uint32_t af[4][4], bh[4][2], bl[4][2];
                const int arow_off = (lane & 15);
                const int akb = ks * 32 + ((lane >> 4) << 4);
                const int bkb = ch * 64 + ks * 32 + (((lane >> 3) & 1) << 4);

#pragma unroll
                for (int mt = 0; mt < 4; ++mt)
                    ldsm_x4(af[mt], smaddr(&sAh[(wm + mt * 16 + arow_off) * AROW]) + akb);
#pragma unroll
                for (int nt = 0; nt < 4; ++nt)
                    ldsm_x2(bh[nt], smaddr(&sBh[(wn + nt * 8 + (lane & 7)) * KROW]) + bkb);
#pragma unroll
                for (int mt = 0; mt < 4; ++mt)
#pragma unroll
                    for (int nt = 0; nt < 4; ++nt) mma_bf16(acc[mt][nt], af[mt], bh[nt]);

#pragma unroll
                for (int nt = 0; nt < 4; ++nt)
                    ldsm_x2(bl[nt], smaddr(&sBl[(wn + nt * 8 + (lane & 7)) * KROW]) + bkb);
#pragma unroll
                for (int mt = 0; mt < 4; ++mt)
#pragma unroll
                    for (int nt = 0; nt < 4; ++nt) mma_bf16(acc[mt][nt], af[mt], bl[nt]);

#pragma unroll
                for (int mt = 0; mt < 4; ++mt)
                    ldsm_x4(af[mt], smaddr(&sAl[(wm + mt * 16 + arow_off) * AROW]) + akb);
#pragma unroll
                for (int mt = 0; mt < 4; ++mt)
#pragma unroll
                    for (int nt = 0; nt < 4; ++nt) mma_bf16(acc[mt][nt], af[mt], bh[nt]);
            }
            __syncthreads();
        }

#pragma unroll
        for (int mt = 0; mt < 4; ++mt) {
#pragma unroll
            for (int nt = 0; nt < 4; ++nt) {
                int r = wm + mt * 16 + (lane >> 2);
                int c = wn + nt * 8 + ((lane & 3) << 1);
                float2 v0 = make_float2(SCALE * acc[mt][nt][0], SCALE * acc[mt][nt][1]);
                float2 v1 = make_float2(SCALE * acc[mt][nt][2], SCALE * acc[mt][nt][3]);
                *(float2*)&C[(size_t)r * SS + c]       = v0;
                *(float2*)&C[(size_t)(r + 8) * SS + c] = v1;
            }
        }
    }
}

// AV (NN core + heavy-first scheduling)
__global__ __launch_bounds__(256, 2) void av_mma(
    const float* __restrict__ attn, const float* __restrict__ v,
    float* __restrict__ o)
{
    const int ry = 15 - (int)blockIdx.y;       // heavy first (LPT)
    const int bh = blockIdx.z;
    const int h = bh % HH, b = bh / HH, kv = h / GG;
    const float* A = attn + (size_t)bh * SS * SS + (size_t)ry * 128 * SS;
    const float* B = v + ((size_t)b * SS * KVH + kv) * HD;
    float* C = o + ((size_t)b * SS * HH + h) * HD
                 + (size_t)ry * 128 * (HH * HD);
    const int K = (ry + 1) * 128;
    gemm_core<false>(A, SS, B, KVH * HD, C, HH * HD, K, 1.0f);
}

// ---------------------------------------------------------------------------
// Fused RMSNorm + RoPE, in place (fp32).
// ---------------------------------------------------------------------------
__global__ __launch_bounds__(128) void normrope_kernel(
    float* __restrict__ data, const float* __restrict__ w,
    const float* __restrict__ cosb, const float* __restrict__ sinb,
    int nheads)
{
    const int idx = blockIdx.x;
    const int h = idx % nheads;
    const int s = (idx / nheads) % SS;
    const int b = idx / (nheads * SS);
    const int t = threadIdx.x;

    float* ptr = data + (((size_t)b * SS + s) * nheads + h) * HD;
    float v = ptr[t];

    float ss = v * v;
#pragma unroll
    for (int o = 16; o; o >>= 1) ss += __shfl_xor_sync(0xffffffffu, ss, o);

    __shared__ float ws[4];
    __shared__ float sh[128];
    const int lane = t & 31, wid = t >> 5;
    if (lane == 0) ws[wid] = ss;
    __syncthreads();
    float var = (ws[0] + ws[1] + ws[2] + ws[3]) * (1.0f / HD);
    float xn = v * rsqrtf(var + 1e-6f) * w[t];
    sh[t] = xn;
    __syncthreads();
    float rot = (t < 64) ? -sh[t + 64] : sh[t - 64];

    const float* cp = cosb + ((size_t)b * SS + s) * HD;
    const float* sp = sinb + ((size_t)b * SS + s) * HD;
    ptr[t] = xn * cp[t] + rot * sp[t];
}

// ---------------------------------------------------------------------------
// Row softmax (causal), register-resident, span-only writes, __expf.
// ---------------------------------------------------------------------------
__global__ __launch_bounds__(256) void softmax_kernel(float* __restrict__ attn)
{
    __shared__ float redm[8];
    __shared__ float reds[8];
    const int row = blockIdx.x;
    const int qi = row & (SS - 1);
    const int valid = qi + 1;
    const int span = ((qi >> 7) + 1) << 7;
    float* base = attn + (size_t)row * SS;
    const int tid = threadIdx.x;
    const int lane = tid & 31, wrp = tid >> 5;

    float4 r0, r1;
    const int t0 = tid * 4;
    const int t1 = t0 + 1024;
    const bool a0 = (t0 < span);
    const bool a1 = (t1 < span);

    float m = -1e30f;
    if (a0) {
        float4 v = *(const float4*)(base + t0);
        v.x = (t0 + 0 < valid) ? v.x : -1e30f;
        v.y = (t0 + 1 < valid) ? v.y : -1e30f;
        v.z = (t0 + 2 < valid) ? v.z : -1e30f;
        v.w = (t0 + 3 < valid) ? v.w : -1e30f;
        r0 = v;
        m = fmaxf(m, fmaxf(fmaxf(v.x, v.y), fmaxf(v.z, v.w)));
    }
    if (a1) {
        float4 v = *(const float4*)(base + t1);
        v.x = (t1 + 0 < valid) ? v.x : -1e30f;
        v.y = (t1 + 1 < valid) ? v.y : -1e30f;
        v.z = (t1 + 2 < valid) ? v.z : -1e30f;
        v.w = (t1 + 3 < valid) ? v.w : -1e30f;
        r1 = v;
        m = fmaxf(m, fmaxf(fmaxf(v.x, v.y), fmaxf(v.z, v.w)));
    }
#pragma unroll
    for (int o = 16; o; o >>= 1) m = fmaxf(m, __shfl_xor_sync(0xffffffffu, m, o));
    if (lane == 0) redm[wrp] = m;
    __syncthreads();
    float mx = redm[0];
#pragma unroll
    for (int i = 1; i < 8; ++i) mx = fmaxf(mx, redm[i]);

    float sum = 0.f;
    if (a0) {
        r0.x = __expf(r0.x - mx); r0.y = __expf(r0.y - mx);
        r0.z = __expf(r0.z - mx); r0.w = __expf(r0.w - mx);
        sum += r0.x + r0.y + r0.z + r0.w;
    }
    if (a1) {
        r1.x = __expf(r1.x - mx); r1.y = __expf(r1.y - mx);
        r1.z = __expf(r1.z - mx); r1.w = __expf(r1.w - mx);
        sum += r1.x + r1.y + r1.z + r1.w;
    }
#pragma unroll
    for (int o = 16; o; o >>= 1) sum += __shfl_xor_sync(0xffffffffu, sum, o);
    if (lane == 0) reds[wrp] = sum;
    __syncthreads();
    float tot = reds[0] + reds[1] + reds[2] + reds[3]
              + reds[4] + reds[5] + reds[6] + reds[7];
    const float inv = 1.0f / tot;

    if (a0) {
        r0.x *= inv; r0.y *= inv; r0.z *= inv; r0.w *= inv;
        *(float4*)(base + t0) = r0;
    }
    if (a1) {
        r1.x *= inv; r1.y *= inv; r1.z *= inv; r1.w *= inv;
        *(float4*)(base + t1) = r1;
    }
}

// ---------------- launch ----------------
extern "C" void kernel_launch(void* const* d_in, const int* in_sizes, int n_in,
                              void* d_out, int out_size)
{
    const float* x    = (const float*)d_in[0];
    const float* cosb = (const float*)d_in[1];
    const float* sinb = (const float*)d_in[2];
    // d_in[3] = attention_mask (pure causal; applied analytically)
    const float* wq   = (const float*)d_in[4];
    const float* wk   = (const float*)d_in[5];
    const float* wv   = (const float*)d_in[6];
    const float* wo   = (const float*)d_in[7];
    const float* qw   = (const float*)d_in[8];
    const float* kw   = (const float*)d_in[9];

    float* out  = (float*)d_out;                    // (B,S,H*HD)
    float* attn = out + (size_t)BB * SS * HH * HD;  // (B,H,S,S)

    float *pq, *pk, *pv, *po;
    cudaGetSymbolAddress((void**)&pq, g_q);
    cudaGetSymbolAddress((void**)&pk, g_k);
    cudaGetSymbolAddress((void**)&pv, g_v);
    cudaGetSymbolAddress((void**)&po, g_o);

    cudaFuncSetAttribute(score_pair,
                         cudaFuncAttributeMaxDynamicSharedMemorySize, SCORE_DSM);

    const int BS = BB * SS;   // 4096
    dim3 blk(256);

    // Fused QKV projection + concurrent causal zero-fill (x >= 32 lanes)
    qkv_mma<<<dim3(36, BS / 128), blk>>>(x, wq, wk, wv, pq, pk, pv, attn);

    // RMSNorm + RoPE (in place, fp32)
    normrope_kernel<<<BB * SS * HH, 128>>>(pq, qw, cosb, sinb, HH);
    normrope_kernel<<<BB * SS * KVH, 128>>>(pk, kw, cosb, sinb, KVH);

    // Scores: GQA-paired, lower triangle only (zeros pre-filled)
    score_pair<<<dim3(SS / 128, SS / 128, BB * KVH), blk, SCORE_DSM>>>(pq, pk, attn);

    // Softmax (register-resident, span-only), AV (heavy-first)
    softmax_kernel<<<BB * HH * SS, 256>>>(attn);
    av_mma<<<dim3(1, 16, BB * HH), blk>>>(attn, pv, po);

    // Output projection
    proj_mma<<<dim3(DD / 128, BS / 128), blk>>>(
        HH * HD, po, HH * HD, wo, HH * HD, out, DD);
}